// round 4
// baseline (speedup 1.0000x reference)
#include <cuda_runtime.h>

#define N_PTS   65536
#define M_CENT  2048
#define KNN     32
#define IN_DIM  40
#define H1D     64
#define H2D     128
#define OUTD    128
#define NROWS   (M_CENT*KNN)   // 65536

// ---------------- scratch (device globals; no allocation allowed) ----------------
__device__ float  g_h1[NROWS*H1D];      // 16 MB
__device__ float  g_h2[NROWS*H2D];      // 32 MB
__device__ float2 g_rel[NROWS];         // 512 KB
__device__ float2 g_cent[M_CENT];
__device__ float  g_s1[H1D], g_ss1[H1D], g_s2[H2D], g_ss2[H2D];

// ---------------- helpers ----------------
__device__ __forceinline__ unsigned smem_u32(const void* p) {
    return (unsigned)__cvta_generic_to_shared(p);
}
__device__ __forceinline__ unsigned mapa_rank(unsigned laddr, unsigned r) {
    unsigned a;
    asm("mapa.shared::cluster.u32 %0, %1, %2;" : "=r"(a) : "r"(laddr), "r"(r));
    return a;
}
__device__ __forceinline__ unsigned long long f32x2_add(unsigned long long a, unsigned long long b) {
    unsigned long long r;
    asm("add.rn.f32x2 %0, %1, %2;" : "=l"(r) : "l"(a), "l"(b));
    return r;
}
__device__ __forceinline__ unsigned long long f32x2_mul(unsigned long long a, unsigned long long b) {
    unsigned long long r;
    asm("mul.rn.f32x2 %0, %1, %2;" : "=l"(r) : "l"(a), "l"(b));
    return r;
}
__device__ __forceinline__ unsigned long long pk2(float l, float h) {
    unsigned long long r;
    asm("mov.b64 %0, {%1, %2};" : "=l"(r) : "f"(l), "f"(h));
    return r;
}
__device__ __forceinline__ float lo_f(unsigned long long v) { return __uint_as_float((unsigned)v); }
__device__ __forceinline__ float hi_f(unsigned long long v) { return __uint_as_float((unsigned)(v >> 32)); }

__device__ __forceinline__ void st_cluster_u64(unsigned addr, unsigned long long v) {
    asm volatile("st.shared::cluster.b64 [%0], %1;" :: "r"(addr), "l"(v) : "memory");
}
// remote arrive (release, cluster scope) on an mbarrier living in target_rank's smem
__device__ __forceinline__ void mbar_arrive_remote(unsigned local_addr, unsigned target_rank) {
    asm volatile(
        "{\n\t"
        ".reg .b32 ra;\n\t"
        "mapa.shared::cluster.u32 ra, %0, %1;\n\t"
        "mbarrier.arrive.release.cluster.shared::cluster.b64 _, [ra];\n\t"
        "}" :: "r"(local_addr), "r"(target_rank) : "memory");
}
// local wait with cluster-scope acquire (pairs with remote release-arrives)
__device__ __forceinline__ void mbar_wait_acq(unsigned addr, unsigned par) {
    asm volatile(
        "{\n\t"
        ".reg .pred P;\n\t"
        "WL_%=:\n\t"
        "mbarrier.try_wait.parity.acquire.cluster.shared::cta.b64 P, [%0], %1, 0x989680;\n\t"
        "@P bra WD_%=;\n\t"
        "bra WL_%=;\n\t"
        "WD_%=:\n\t"
        "}" :: "r"(addr), "r"(par) : "memory");
}

// ---------------- init: zero BN accumulators (graph replays!) ----------------
__global__ void k_init() {
    int t = threadIdx.x;
    if (t < H1D) { g_s1[t] = 0.f; g_ss1[t] = 0.f; }
    if (t < H2D) { g_s2[t] = 0.f; g_ss2[t] = 0.f; }
}

// ---------------- FPS: 8-CTA cluster; mbarrier gather/scatter tree ----------------
#define FPS_C 8
#define FPS_T 512
#define FPS_PPT 16                       // points per thread
#define FPS_PP2 (FPS_PPT/2)              // packed pairs

__global__ void __cluster_dims__(FPS_C,1,1) __launch_bounds__(FPS_T,1)
k_fps(const float2* __restrict__ pts, float* __restrict__ cent_dout, int write_dout)
{
    __shared__ unsigned long long s_wkey[FPS_T/32];   // per-warp best key
    __shared__ unsigned long long s_wxy[FPS_T/32];    // per-warp best coords
    __shared__ unsigned long long s_mbox_key[FPS_C];  // CTA0's gather mailbox
    __shared__ unsigned long long s_mbox_xy[FPS_C];
    __shared__ unsigned long long s_res;              // winner coords (written remotely)
    __shared__ unsigned long long mb_gather;          // mbarrier, 8 arrivals/phase (used on rank 0)
    __shared__ unsigned long long mb_result;          // mbarrier, 1 arrival/phase

    unsigned rank; asm("mov.u32 %0, %%cluster_ctarank;" : "=r"(rank));
    int tid  = threadIdx.x;
    int gtid = (int)rank * FPS_T + tid;
    int base = gtid * FPS_PPT;

    unsigned mb_gather_a = smem_u32(&mb_gather);
    unsigned mb_result_a = smem_u32(&mb_result);

    if (tid == 0) {
        asm volatile("mbarrier.init.shared.b64 [%0], %1;" :: "r"(mb_gather_a), "r"(FPS_C) : "memory");
        asm volatile("mbarrier.init.shared.b64 [%0], %1;" :: "r"(mb_result_a), "r"(1) : "memory");
    }

    // register-resident points (packed pairs) + min-dist^2
    unsigned long long px2[FPS_PP2], py2[FPS_PP2];
    float d2[FPS_PPT];
    {
        const float4* p4 = (const float4*)pts;
        #pragma unroll
        for (int i = 0; i < FPS_PP2; i++) {
            float4 v = p4[(base >> 1) + i];
            px2[i] = pk2(v.x, v.z);
            py2[i] = pk2(v.y, v.w);
            d2[2*i]   = __int_as_float(0x7f800000);
            d2[2*i+1] = __int_as_float(0x7f800000);
        }
    }

    float2 p0 = pts[0];
    float cx = p0.x, cy = p0.y;
    if (rank == 0 && tid == 0) {
        g_cent[0] = p0;
        if (write_dout) { cent_dout[0] = p0.x; cent_dout[1] = p0.y; }
    }

    // mbarrier init visible cluster-wide before any remote arrive
    __syncthreads();
    asm volatile("barrier.cluster.arrive.aligned;" ::: "memory");
    asm volatile("barrier.cluster.wait.aligned;"   ::: "memory");

    unsigned long long tiebreak = (unsigned long long)(0xFFFFFFFFu - (unsigned)gtid);

    for (int s = 1; s < M_CENT; s++) {
        unsigned par = (unsigned)((s - 1) & 1);
        unsigned long long ncx2 = pk2(-cx, -cx);
        unsigned long long ncy2 = pk2(-cy, -cy);

        // scan: update running min-dist^2, track max of mins.
        // prev center's own dd == 0 exactly -> implicit dist.at[prev].set(0)
        float bm = -1.0f;
        #pragma unroll
        for (int i = 0; i < FPS_PP2; i++) {
            unsigned long long dx2 = f32x2_add(px2[i], ncx2);
            unsigned long long dy2 = f32x2_add(py2[i], ncy2);
            unsigned long long dd2 = f32x2_add(f32x2_mul(dx2, dx2), f32x2_mul(dy2, dy2));
            float nd0 = fminf(d2[2*i],   lo_f(dd2));
            float nd1 = fminf(d2[2*i+1], hi_f(dd2));
            d2[2*i]   = nd0;
            d2[2*i+1] = nd1;
            bm = fmaxf(bm, nd0);
            bm = fmaxf(bm, nd1);
        }
        // recover coords of FIRST j matching bm (reverse select chain -> smallest j wins)
        float bx = 0.f, by = 0.f;
        #pragma unroll
        for (int i = FPS_PP2 - 1; i >= 0; i--) {
            if (d2[2*i+1] == bm) { bx = hi_f(px2[i]); by = hi_f(py2[i]); }
            if (d2[2*i]   == bm) { bx = lo_f(px2[i]); by = lo_f(py2[i]); }
        }
        // map to reference's dist domain: sqrt(d2 + 1e-12); tie-break by thread order
        float sv = sqrtf(__fadd_rn(bm, 1e-12f));
        unsigned long long key = ((unsigned long long)__float_as_uint(sv) << 32) | tiebreak;
        unsigned long long xy  = pk2(bx, by);

        // warp reduce (key + coords payload)
        #pragma unroll
        for (int off = 16; off; off >>= 1) {
            unsigned long long ok = __shfl_down_sync(0xFFFFFFFFu, key, off);
            unsigned long long oy = __shfl_down_sync(0xFFFFFFFFu, xy,  off);
            if (ok > key) { key = ok; xy = oy; }
        }
        if ((tid & 31) == 0) { s_wkey[tid >> 5] = key; s_wxy[tid >> 5] = xy; }
        __syncthreads();   // sole block-wide sync: also backpressures slot reuse

        if (tid < 16) {
            key = s_wkey[tid]; xy = s_wxy[tid];
            #pragma unroll
            for (int off = 8; off; off >>= 1) {
                unsigned long long ok = __shfl_down_sync(0xFFFFu, key, off, 16);
                unsigned long long oy = __shfl_down_sync(0xFFFFu, xy,  off, 16);
                if (ok > key) { key = ok; xy = oy; }
            }
            if (tid == 0) {
                // push CTA-best to CTA0's mailbox, then release-arrive on CTA0's gather mbar
                st_cluster_u64(mapa_rank(smem_u32(&s_mbox_key[rank]), 0), key);
                st_cluster_u64(mapa_rank(smem_u32(&s_mbox_xy[rank]),  0), xy);
                mbar_arrive_remote(mb_gather_a, 0);
            }
        }
        if (rank == 0 && tid < 8) {
            mbar_wait_acq(mb_gather_a, par);
            unsigned long long rkey = s_mbox_key[tid];   // local LDS on CTA0
            unsigned long long rxy  = s_mbox_xy[tid];
            #pragma unroll
            for (int off = 4; off; off >>= 1) {
                unsigned long long ok = __shfl_down_sync(0xFFu, rkey, off, 8);
                unsigned long long oy = __shfl_down_sync(0xFFu, rxy,  off, 8);
                if (ok > rkey) { rkey = ok; rxy = oy; }
            }
            rxy = __shfl_sync(0xFFu, rxy, 0, 8);
            // scatter winner to every CTA's result slot + release-arrive its result mbar
            st_cluster_u64(mapa_rank(smem_u32(&s_res), (unsigned)tid), rxy);
            mbar_arrive_remote(mb_result_a, (unsigned)tid);
            if (tid == 0) {
                float wx = lo_f(rxy), wy = hi_f(rxy);
                g_cent[s] = make_float2(wx, wy);
                if (write_dout) { cent_dout[2*s] = wx; cent_dout[2*s+1] = wy; }
            }
        }
        // every thread waits directly on its CTA's result barrier (no trailing syncthreads)
        mbar_wait_acq(mb_result_a, par);
        unsigned long long w = s_res;
        cx = lo_f(w); cy = hi_f(w);
    }
}

// ---------------- ball query: 1 warp / centroid, first-K by index ----------------
__global__ __launch_bounds__(1024) void k_ballquery(const float2* __restrict__ pts)
{
    int gw   = (blockIdx.x * blockDim.x + threadIdx.x) >> 5;
    int lane = threadIdx.x & 31;
    if (gw >= M_CENT) return;

    float2 c  = g_cent[gw];
    float  c2 = __fadd_rn(__fmul_rn(c.x,c.x), __fmul_rn(c.y,c.y));

    int   cnt  = 0;
    bool  have = false;
    float fx = 0.f, fy = 0.f;

    for (int b = 0; b < N_PTS; b += 32) {
        float2 p   = pts[b + lane];
        float  p2  = __fadd_rn(__fmul_rn(p.x,p.x), __fmul_rn(p.y,p.y));
        float  dot = __fadd_rn(__fmul_rn(c.x,p.x), __fmul_rn(c.y,p.y));
        float  dd  = __fsub_rn(__fadd_rn(c2, p2), __fmul_rn(2.0f, dot));
        bool hit = (dd <= 0.0025f);
        unsigned m = __ballot_sync(0xFFFFFFFFu, hit);
        float rx = __fsub_rn(p.x, c.x), ry = __fsub_rn(p.y, c.y);
        if (!have && m) {
            int src = __ffs(m) - 1;
            fx = __shfl_sync(0xFFFFFFFFu, rx, src);
            fy = __shfl_sync(0xFFFFFFFFu, ry, src);
            have = true;
        }
        int pos = cnt + __popc(m & ((1u << lane) - 1u));
        if (hit && pos < KNN) g_rel[gw*KNN + pos] = make_float2(rx, ry);
        cnt += __popc(m);
        if (cnt >= KNN) break;
    }
    for (int s2 = cnt + lane; s2 < KNN; s2 += 32)
        g_rel[gw*KNN + s2] = make_float2(fx, fy);
}

// ---------------- layer1: freq-encode + [65536x40]@[40x64] + b1 ----------------
__global__ __launch_bounds__(128) void k_layer1(const float* __restrict__ W1,
                                                const float* __restrict__ b1)
{
    __shared__ float ws[IN_DIM*H1D];   // 10 KB
    __shared__ float bs[H1D];
    int tid = threadIdx.x;
    for (int i = tid; i < IN_DIM*H1D; i += 128) ws[i] = W1[i];
    if (tid < H1D) bs[tid] = b1[tid];
    __syncthreads();

    int r = blockIdx.x * 128 + tid;
    float2 q = g_rel[r];

    float acc[H1D];
    #pragma unroll
    for (int j = 0; j < H1D; j++) acc[j] = bs[j];

    for (int f = 0; f < 10; f++) {
        float fr = 3.14159265358979f * (float)(1 << f);
        float e0, e1, e2, e3;
        sincosf(__fmul_rn(q.x, fr), &e0, &e1);
        sincosf(__fmul_rn(q.y, fr), &e2, &e3);
        const float* w0 = &ws[(4*f + 0)*H1D];
        const float* w1 = &ws[(4*f + 1)*H1D];
        const float* w2 = &ws[(4*f + 2)*H1D];
        const float* w3 = &ws[(4*f + 3)*H1D];
        #pragma unroll
        for (int j = 0; j < H1D; j++) {
            acc[j] = fmaf(e0, w0[j], acc[j]);
            acc[j] = fmaf(e1, w1[j], acc[j]);
            acc[j] = fmaf(e2, w2[j], acc[j]);
            acc[j] = fmaf(e3, w3[j], acc[j]);
        }
    }
    float4* o = (float4*)&g_h1[(size_t)r * H1D];
    #pragma unroll
    for (int j = 0; j < H1D/4; j++)
        o[j] = make_float4(acc[4*j], acc[4*j+1], acc[4*j+2], acc[4*j+3]);
}

// ---------------- column sum / sumsq reduction ----------------
template <int C>
__device__ __forceinline__ void colreduce_body(const float* __restrict__ src,
                                               float* __restrict__ outs,
                                               float* __restrict__ outss)
{
    __shared__ float sh_s[256], sh_q[256];
    int tid = threadIdx.x;
    int col = tid & (C - 1);
    int sub = tid / C;
    const int L = 256 / C;
    int row0 = blockIdx.x * (NROWS / 256);
    float s = 0.f, q = 0.f;
    for (int r = sub; r < NROWS/256; r += L) {
        float v = src[(size_t)(row0 + r) * C + col];
        s += v;
        q  = fmaf(v, v, q);
    }
    sh_s[tid] = s; sh_q[tid] = q;
    __syncthreads();
    if (tid < C) {
        float ts = 0.f, tq = 0.f;
        #pragma unroll
        for (int u = 0; u < L; u++) { ts += sh_s[u*C + tid]; tq += sh_q[u*C + tid]; }
        atomicAdd(&outs[tid], ts);
        atomicAdd(&outss[tid], tq);
    }
}
__global__ __launch_bounds__(256) void k_red1() { colreduce_body<H1D>(g_h1, g_s1, g_ss1); }
__global__ __launch_bounds__(256) void k_red2() { colreduce_body<H2D>(g_h2, g_s2, g_ss2); }

// ---------------- layer2: BN1+ReLU then [65536x64]@[64x128] + b2 ----------------
__global__ __launch_bounds__(128) void k_layer2(const float* __restrict__ W2,
                                                const float* __restrict__ b2,
                                                const float* __restrict__ g1,
                                                const float* __restrict__ be1)
{
    __shared__ float xs[32*H1D];
    __shared__ float sc[H1D], sh[H1D];
    int tid = threadIdx.x;
    if (tid < H1D) {
        float m  = g_s1[tid]  * (1.0f/NROWS);
        float v  = g_ss1[tid] * (1.0f/NROWS) - m*m;
        float rs = rsqrtf(v + 1e-5f);
        float scale = g1[tid] * rs;
        sc[tid] = scale;
        sh[tid] = be1[tid] - m * scale;
    }
    __syncthreads();

    int row0 = blockIdx.x * 32;
    for (int t = tid; t < 32*H1D; t += 128) {
        int c = t & (H1D - 1);
        float v = g_h1[(size_t)row0 * H1D + t];
        xs[t] = fmaxf(fmaf(v, sc[c], sh[c]), 0.0f);
    }
    __syncthreads();

    int j = tid;
    float acc[32];
    float bj = b2[j];
    #pragma unroll
    for (int r = 0; r < 32; r++) acc[r] = bj;
    for (int i = 0; i < H1D; i++) {
        float w = __ldg(&W2[i*H2D + j]);
        #pragma unroll
        for (int r = 0; r < 32; r++)
            acc[r] = fmaf(xs[r*H1D + i], w, acc[r]);
    }
    #pragma unroll
    for (int r = 0; r < 32; r++)
        g_h2[(size_t)(row0 + r) * H2D + j] = acc[r];
}

// ---------------- layer3: BN2+ReLU, [32x128]@[128x128]+b3, max over 32 ----------------
__global__ __launch_bounds__(128) void k_layer3(const float* __restrict__ W3,
                                                const float* __restrict__ b3,
                                                const float* __restrict__ g2,
                                                const float* __restrict__ be2,
                                                float* __restrict__ out)
{
    __shared__ float xs[32*H2D];
    __shared__ float sc[H2D], sh[H2D];
    int tid = threadIdx.x;
    {
        float m  = g_s2[tid]  * (1.0f/NROWS);
        float v  = g_ss2[tid] * (1.0f/NROWS) - m*m;
        float rs = rsqrtf(v + 1e-5f);
        float scale = g2[tid] * rs;
        sc[tid] = scale;
        sh[tid] = be2[tid] - m * scale;
    }
    __syncthreads();

    int row0 = blockIdx.x * 32;
    for (int t = tid; t < 32*H2D; t += 128) {
        int c = t & (H2D - 1);
        float v = g_h2[(size_t)row0 * H2D + t];
        xs[t] = fmaxf(fmaf(v, sc[c], sh[c]), 0.0f);
    }
    __syncthreads();

    int j = tid;
    float acc[32];
    float bj = b3[j];
    #pragma unroll
    for (int r = 0; r < 32; r++) acc[r] = bj;
    for (int i = 0; i < H2D; i++) {
        float w = __ldg(&W3[i*OUTD + j]);
        #pragma unroll
        for (int r = 0; r < 32; r++)
            acc[r] = fmaf(xs[r*H2D + i], w, acc[r]);
    }
    float mv = acc[0];
    #pragma unroll
    for (int r = 1; r < 32; r++) mv = fmaxf(mv, acc[r]);
    out[(size_t)blockIdx.x * OUTD + j] = mv;
}

// ---------------- launch ----------------
extern "C" void kernel_launch(void* const* d_in, const int* in_sizes, int n_in,
                              void* d_out, int out_size)
{
    const float2* pts = (const float2*)d_in[0];
    const float* W1  = (const float*)d_in[1];
    const float* b1  = (const float*)d_in[2];
    const float* g1  = (const float*)d_in[3];
    const float* be1 = (const float*)d_in[4];
    const float* W2  = (const float*)d_in[5];
    const float* b2  = (const float*)d_in[6];
    const float* g2  = (const float*)d_in[7];
    const float* be2 = (const float*)d_in[8];
    const float* W3  = (const float*)d_in[9];
    const float* b3  = (const float*)d_in[10];

    float* out = (float*)d_out;
    float* cent_out = out + (size_t)M_CENT * OUTD;
    int wd = (out_size >= M_CENT*OUTD + M_CENT*2) ? 1 : 0;

    k_init<<<1, 128>>>();
    k_fps<<<FPS_C, FPS_T>>>(pts, cent_out, wd);
    k_ballquery<<<64, 1024>>>(pts);
    k_layer1<<<NROWS/128, 128>>>(W1, b1);
    k_red1<<<256, 256>>>();
    k_layer2<<<NROWS/32, 128>>>(W2, b2, g1, be1);
    k_red2<<<256, 256>>>();
    k_layer3<<<M_CENT, 128>>>(W3, b3, g2, be2, out);
}

// round 5
// speedup vs baseline: 1.3490x; 1.3490x over previous
#include <cuda_runtime.h>

#define N_PTS   65536
#define M_CENT  2048
#define KNN     32
#define IN_DIM  40
#define H1D     64
#define H2D     128
#define OUTD    128
#define NROWS   (M_CENT*KNN)   // 65536

// ---------------- scratch (device globals; no allocation allowed) ----------------
__device__ float  g_h1[NROWS*H1D];      // 16 MB
__device__ float  g_h2[NROWS*H2D];      // 32 MB
__device__ float2 g_rel[NROWS];         // 512 KB
__device__ float2 g_cent[M_CENT];
__device__ float  g_s1[H1D], g_ss1[H1D], g_s2[H2D], g_ss2[H2D];

// ---------------- helpers ----------------
__device__ __forceinline__ unsigned smem_u32(const void* p) {
    return (unsigned)__cvta_generic_to_shared(p);
}
__device__ __forceinline__ unsigned mapa_rank(unsigned laddr, unsigned r) {
    unsigned a;
    asm("mapa.shared::cluster.u32 %0, %1, %2;" : "=r"(a) : "r"(laddr), "r"(r));
    return a;
}
__device__ __forceinline__ unsigned long long f32x2_add(unsigned long long a, unsigned long long b) {
    unsigned long long r;
    asm("add.rn.f32x2 %0, %1, %2;" : "=l"(r) : "l"(a), "l"(b));
    return r;
}
__device__ __forceinline__ unsigned long long f32x2_mul(unsigned long long a, unsigned long long b) {
    unsigned long long r;
    asm("mul.rn.f32x2 %0, %1, %2;" : "=l"(r) : "l"(a), "l"(b));
    return r;
}
__device__ __forceinline__ unsigned long long pk2(float l, float h) {
    unsigned long long r;
    asm("mov.b64 %0, {%1, %2};" : "=l"(r) : "f"(l), "f"(h));
    return r;
}
__device__ __forceinline__ float lo_f(unsigned long long v) { return __uint_as_float((unsigned)v); }
__device__ __forceinline__ float hi_f(unsigned long long v) { return __uint_as_float((unsigned)(v >> 32)); }

// ---------------- init: zero BN accumulators (graph replays!) ----------------
__global__ void k_init() {
    int t = threadIdx.x;
    if (t < H1D) { g_s1[t] = 0.f; g_ss1[t] = 0.f; }
    if (t < H2D) { g_s2[t] = 0.f; g_ss2[t] = 0.f; }
}

// ---------------- FPS: 8-CTA cluster; 256 thr/CTA; one cluster barrier/iter ----------------
#define FPS_C 8
#define FPS_T 256
#define FPS_PPT 32                       // points per thread
#define FPS_PP2 (FPS_PPT/2)              // packed pairs
#define FPS_W  (FPS_T/32)                // 8 warps

__global__ void __cluster_dims__(FPS_C,1,1) __launch_bounds__(FPS_T,1)
k_fps(const float2* __restrict__ pts, float* __restrict__ cent_dout, int write_dout)
{
    __shared__ unsigned long long s_wkey[FPS_W];      // per-warp best key
    __shared__ unsigned long long s_wxy[FPS_W];       // per-warp best coords
    __shared__ alignas(16) unsigned long long s_b[2][2];  // CTA best: [parity]{key, xy}

    unsigned rank; asm("mov.u32 %0, %%cluster_ctarank;" : "=r"(rank));
    int tid  = threadIdx.x;
    int lane = tid & 31;
    int gtid = (int)rank * FPS_T + tid;
    int base = gtid * FPS_PPT;

    // register-resident points (packed pairs) + min-dist^2
    unsigned long long px2[FPS_PP2], py2[FPS_PP2];
    float d2[FPS_PPT];
    {
        const float4* p4 = (const float4*)pts;
        #pragma unroll
        for (int i = 0; i < FPS_PP2; i++) {
            float4 v = p4[(base >> 1) + i];
            px2[i] = pk2(v.x, v.z);
            py2[i] = pk2(v.y, v.w);
            d2[2*i]   = __int_as_float(0x7f800000);
            d2[2*i+1] = __int_as_float(0x7f800000);
        }
    }

    float2 p0 = pts[0];
    float cx = p0.x, cy = p0.y;
    if (rank == 0 && tid == 0) {
        g_cent[0] = p0;
        if (write_dout) { cent_dout[0] = p0.x; cent_dout[1] = p0.y; }
    }

    unsigned long long tiebreak = (unsigned long long)(0xFFFFFFFFu - (unsigned)gtid);

    for (int s = 1; s < M_CENT; s++) {
        int p = s & 1;
        unsigned long long ncx2 = pk2(-cx, -cx);
        unsigned long long ncy2 = pk2(-cy, -cy);

        // scan: update running min-dist^2, track max of mins.
        // prev center's own dd == 0 exactly -> implicit dist.at[prev].set(0)
        float bm = -1.0f;
        #pragma unroll
        for (int i = 0; i < FPS_PP2; i++) {
            unsigned long long dx2 = f32x2_add(px2[i], ncx2);
            unsigned long long dy2 = f32x2_add(py2[i], ncy2);
            unsigned long long dd2 = f32x2_add(f32x2_mul(dx2, dx2), f32x2_mul(dy2, dy2));
            float nd0 = fminf(d2[2*i],   lo_f(dd2));
            float nd1 = fminf(d2[2*i+1], hi_f(dd2));
            d2[2*i]   = nd0;
            d2[2*i+1] = nd1;
            bm = fmaxf(bm, nd0);
            bm = fmaxf(bm, nd1);
        }
        // recover coords of FIRST j matching bm (reverse select chain -> smallest j wins)
        float bx = 0.f, by = 0.f;
        #pragma unroll
        for (int i = FPS_PP2 - 1; i >= 0; i--) {
            if (d2[2*i+1] == bm) { bx = hi_f(px2[i]); by = hi_f(py2[i]); }
            if (d2[2*i]   == bm) { bx = lo_f(px2[i]); by = lo_f(py2[i]); }
        }
        // map to reference's dist domain: sqrt(d2 + 1e-12); tie-break by thread order
        float sv = sqrtf(__fadd_rn(bm, 1e-12f));
        unsigned long long key = ((unsigned long long)__float_as_uint(sv) << 32) | tiebreak;
        unsigned long long xy  = pk2(bx, by);

        // warp reduce (key + coords payload)
        #pragma unroll
        for (int off = 16; off; off >>= 1) {
            unsigned long long ok = __shfl_down_sync(0xFFFFFFFFu, key, off);
            unsigned long long oy = __shfl_down_sync(0xFFFFFFFFu, xy,  off);
            if (ok > key) { key = ok; xy = oy; }
        }
        if (lane == 0) { s_wkey[tid >> 5] = key; s_wxy[tid >> 5] = xy; }
        __syncthreads();

        // warp 0: reduce the 8 warp-bests, publish CTA-best to mailbox slot
        if (tid < 8) {
            key = s_wkey[tid]; xy = s_wxy[tid];
            #pragma unroll
            for (int off = 4; off; off >>= 1) {
                unsigned long long ok = __shfl_down_sync(0xFFu, key, off, 8);
                unsigned long long oy = __shfl_down_sync(0xFFu, xy,  off, 8);
                if (ok > key) { key = ok; xy = oy; }
            }
            if (tid == 0) {
                asm volatile("st.shared.v2.b64 [%0], {%1, %2};"
                             :: "r"(smem_u32(&s_b[p][0])), "l"(key), "l"(xy) : "memory");
            }
        }
        // single cluster barrier: releases local mailbox store, acquires peers'
        asm volatile("barrier.cluster.arrive.aligned;" ::: "memory");
        asm volatile("barrier.cluster.wait.aligned;"   ::: "memory");

        // EVERY warp gathers all 8 CTA-bests itself (no block sync needed after)
        unsigned long long rkey = 0ull, rxy = 0ull;
        if (lane < 8) {
            unsigned ra = mapa_rank(smem_u32(&s_b[p][0]), (unsigned)lane);
            asm volatile("ld.shared::cluster.v2.b64 {%0, %1}, [%2];"
                         : "=l"(rkey), "=l"(rxy) : "r"(ra) : "memory");
        }
        #pragma unroll
        for (int off = 4; off; off >>= 1) {
            unsigned long long ok = __shfl_down_sync(0xFFFFFFFFu, rkey, off, 8);
            unsigned long long oy = __shfl_down_sync(0xFFFFFFFFu, rxy,  off, 8);
            if (ok > rkey) { rkey = ok; rxy = oy; }
        }
        rxy = __shfl_sync(0xFFFFFFFFu, rxy, 0);
        cx = lo_f(rxy); cy = hi_f(rxy);

        if (rank == 0 && tid == 0) {
            g_cent[s] = make_float2(cx, cy);
            if (write_dout) { cent_dout[2*s] = cx; cent_dout[2*s+1] = cy; }
        }
    }
}

// ---------------- ball query: 1 warp / centroid, first-K by index ----------------
__global__ __launch_bounds__(1024) void k_ballquery(const float2* __restrict__ pts)
{
    int gw   = (blockIdx.x * blockDim.x + threadIdx.x) >> 5;
    int lane = threadIdx.x & 31;
    if (gw >= M_CENT) return;

    float2 c  = g_cent[gw];
    float  c2 = __fadd_rn(__fmul_rn(c.x,c.x), __fmul_rn(c.y,c.y));

    int   cnt  = 0;
    bool  have = false;
    float fx = 0.f, fy = 0.f;

    for (int b = 0; b < N_PTS; b += 32) {
        float2 p   = pts[b + lane];
        float  p2  = __fadd_rn(__fmul_rn(p.x,p.x), __fmul_rn(p.y,p.y));
        float  dot = __fadd_rn(__fmul_rn(c.x,p.x), __fmul_rn(c.y,p.y));
        float  dd  = __fsub_rn(__fadd_rn(c2, p2), __fmul_rn(2.0f, dot));
        bool hit = (dd <= 0.0025f);
        unsigned m = __ballot_sync(0xFFFFFFFFu, hit);
        float rx = __fsub_rn(p.x, c.x), ry = __fsub_rn(p.y, c.y);
        if (!have && m) {
            int src = __ffs(m) - 1;
            fx = __shfl_sync(0xFFFFFFFFu, rx, src);
            fy = __shfl_sync(0xFFFFFFFFu, ry, src);
            have = true;
        }
        int pos = cnt + __popc(m & ((1u << lane) - 1u));
        if (hit && pos < KNN) g_rel[gw*KNN + pos] = make_float2(rx, ry);
        cnt += __popc(m);
        if (cnt >= KNN) break;
    }
    for (int s2 = cnt + lane; s2 < KNN; s2 += 32)
        g_rel[gw*KNN + s2] = make_float2(fx, fy);
}

// ---------------- layer1: freq-encode + [65536x40]@[40x64] + b1 ----------------
__global__ __launch_bounds__(128) void k_layer1(const float* __restrict__ W1,
                                                const float* __restrict__ b1)
{
    __shared__ float ws[IN_DIM*H1D];   // 10 KB
    __shared__ float bs[H1D];
    int tid = threadIdx.x;
    for (int i = tid; i < IN_DIM*H1D; i += 128) ws[i] = W1[i];
    if (tid < H1D) bs[tid] = b1[tid];
    __syncthreads();

    int r = blockIdx.x * 128 + tid;
    float2 q = g_rel[r];

    float acc[H1D];
    #pragma unroll
    for (int j = 0; j < H1D; j++) acc[j] = bs[j];

    for (int f = 0; f < 10; f++) {
        float fr = 3.14159265358979f * (float)(1 << f);
        float e0, e1, e2, e3;
        sincosf(__fmul_rn(q.x, fr), &e0, &e1);
        sincosf(__fmul_rn(q.y, fr), &e2, &e3);
        const float* w0 = &ws[(4*f + 0)*H1D];
        const float* w1 = &ws[(4*f + 1)*H1D];
        const float* w2 = &ws[(4*f + 2)*H1D];
        const float* w3 = &ws[(4*f + 3)*H1D];
        #pragma unroll
        for (int j = 0; j < H1D; j++) {
            acc[j] = fmaf(e0, w0[j], acc[j]);
            acc[j] = fmaf(e1, w1[j], acc[j]);
            acc[j] = fmaf(e2, w2[j], acc[j]);
            acc[j] = fmaf(e3, w3[j], acc[j]);
        }
    }
    float4* o = (float4*)&g_h1[(size_t)r * H1D];
    #pragma unroll
    for (int j = 0; j < H1D/4; j++)
        o[j] = make_float4(acc[4*j], acc[4*j+1], acc[4*j+2], acc[4*j+3]);
}

// ---------------- column sum / sumsq reduction ----------------
template <int C>
__device__ __forceinline__ void colreduce_body(const float* __restrict__ src,
                                               float* __restrict__ outs,
                                               float* __restrict__ outss)
{
    __shared__ float sh_s[256], sh_q[256];
    int tid = threadIdx.x;
    int col = tid & (C - 1);
    int sub = tid / C;
    const int L = 256 / C;
    int row0 = blockIdx.x * (NROWS / 256);
    float s = 0.f, q = 0.f;
    for (int r = sub; r < NROWS/256; r += L) {
        float v = src[(size_t)(row0 + r) * C + col];
        s += v;
        q  = fmaf(v, v, q);
    }
    sh_s[tid] = s; sh_q[tid] = q;
    __syncthreads();
    if (tid < C) {
        float ts = 0.f, tq = 0.f;
        #pragma unroll
        for (int u = 0; u < L; u++) { ts += sh_s[u*C + tid]; tq += sh_q[u*C + tid]; }
        atomicAdd(&outs[tid], ts);
        atomicAdd(&outss[tid], tq);
    }
}
__global__ __launch_bounds__(256) void k_red1() { colreduce_body<H1D>(g_h1, g_s1, g_ss1); }
__global__ __launch_bounds__(256) void k_red2() { colreduce_body<H2D>(g_h2, g_s2, g_ss2); }

// ---------------- layer2: BN1+ReLU then [65536x64]@[64x128] + b2 ----------------
__global__ __launch_bounds__(128) void k_layer2(const float* __restrict__ W2,
                                                const float* __restrict__ b2,
                                                const float* __restrict__ g1,
                                                const float* __restrict__ be1)
{
    __shared__ float xs[32*H1D];
    __shared__ float sc[H1D], sh[H1D];
    int tid = threadIdx.x;
    if (tid < H1D) {
        float m  = g_s1[tid]  * (1.0f/NROWS);
        float v  = g_ss1[tid] * (1.0f/NROWS) - m*m;
        float rs = rsqrtf(v + 1e-5f);
        float scale = g1[tid] * rs;
        sc[tid] = scale;
        sh[tid] = be1[tid] - m * scale;
    }
    __syncthreads();

    int row0 = blockIdx.x * 32;
    for (int t = tid; t < 32*H1D; t += 128) {
        int c = t & (H1D - 1);
        float v = g_h1[(size_t)row0 * H1D + t];
        xs[t] = fmaxf(fmaf(v, sc[c], sh[c]), 0.0f);
    }
    __syncthreads();

    int j = tid;
    float acc[32];
    float bj = b2[j];
    #pragma unroll
    for (int r = 0; r < 32; r++) acc[r] = bj;
    for (int i = 0; i < H1D; i++) {
        float w = __ldg(&W2[i*H2D + j]);
        #pragma unroll
        for (int r = 0; r < 32; r++)
            acc[r] = fmaf(xs[r*H1D + i], w, acc[r]);
    }
    #pragma unroll
    for (int r = 0; r < 32; r++)
        g_h2[(size_t)(row0 + r) * H2D + j] = acc[r];
}

// ---------------- layer3: BN2+ReLU, [32x128]@[128x128]+b3, max over 32 ----------------
__global__ __launch_bounds__(128) void k_layer3(const float* __restrict__ W3,
                                                const float* __restrict__ b3,
                                                const float* __restrict__ g2,
                                                const float* __restrict__ be2,
                                                float* __restrict__ out)
{
    __shared__ float xs[32*H2D];
    __shared__ float sc[H2D], sh[H2D];
    int tid = threadIdx.x;
    {
        float m  = g_s2[tid]  * (1.0f/NROWS);
        float v  = g_ss2[tid] * (1.0f/NROWS) - m*m;
        float rs = rsqrtf(v + 1e-5f);
        float scale = g2[tid] * rs;
        sc[tid] = scale;
        sh[tid] = be2[tid] - m * scale;
    }
    __syncthreads();

    int row0 = blockIdx.x * 32;
    for (int t = tid; t < 32*H2D; t += 128) {
        int c = t & (H2D - 1);
        float v = g_h2[(size_t)row0 * H2D + t];
        xs[t] = fmaxf(fmaf(v, sc[c], sh[c]), 0.0f);
    }
    __syncthreads();

    int j = tid;
    float acc[32];
    float bj = b3[j];
    #pragma unroll
    for (int r = 0; r < 32; r++) acc[r] = bj;
    for (int i = 0; i < H2D; i++) {
        float w = __ldg(&W3[i*OUTD + j]);
        #pragma unroll
        for (int r = 0; r < 32; r++)
            acc[r] = fmaf(xs[r*H2D + i], w, acc[r]);
    }
    float mv = acc[0];
    #pragma unroll
    for (int r = 1; r < 32; r++) mv = fmaxf(mv, acc[r]);
    out[(size_t)blockIdx.x * OUTD + j] = mv;
}

// ---------------- launch ----------------
extern "C" void kernel_launch(void* const* d_in, const int* in_sizes, int n_in,
                              void* d_out, int out_size)
{
    const float2* pts = (const float2*)d_in[0];
    const float* W1  = (const float*)d_in[1];
    const float* b1  = (const float*)d_in[2];
    const float* g1  = (const float*)d_in[3];
    const float* be1 = (const float*)d_in[4];
    const float* W2  = (const float*)d_in[5];
    const float* b2  = (const float*)d_in[6];
    const float* g2  = (const float*)d_in[7];
    const float* be2 = (const float*)d_in[8];
    const float* W3  = (const float*)d_in[9];
    const float* b3  = (const float*)d_in[10];

    float* out = (float*)d_out;
    float* cent_out = out + (size_t)M_CENT * OUTD;
    int wd = (out_size >= M_CENT*OUTD + M_CENT*2) ? 1 : 0;

    k_init<<<1, 128>>>();
    k_fps<<<FPS_C, FPS_T>>>(pts, cent_out, wd);
    k_ballquery<<<64, 1024>>>(pts);
    k_layer1<<<NROWS/128, 128>>>(W1, b1);
    k_red1<<<256, 256>>>();
    k_layer2<<<NROWS/32, 128>>>(W2, b2, g1, be1);
    k_red2<<<256, 256>>>();
    k_layer3<<<M_CENT, 128>>>(W3, b3, g2, be2, out);
}

// round 6
// speedup vs baseline: 1.4287x; 1.0591x over previous
#include <cuda_runtime.h>

#define N_PTS   65536
#define M_CENT  2048
#define KNN     32
#define IN_DIM  40
#define H1D     64
#define H2D     128
#define OUTD    128
#define NROWS   (M_CENT*KNN)   // 65536

// ---------------- scratch (device globals; no allocation allowed) ----------------
__device__ float  g_h1[NROWS*H1D];      // 16 MB
__device__ float  g_h2[NROWS*H2D];      // 32 MB
__device__ float2 g_rel[NROWS];         // 512 KB
__device__ float2 g_cent[M_CENT];
__device__ float  g_s1[H1D], g_ss1[H1D], g_s2[H2D], g_ss2[H2D];

// ---------------- helpers ----------------
__device__ __forceinline__ unsigned smem_u32(const void* p) {
    return (unsigned)__cvta_generic_to_shared(p);
}
__device__ __forceinline__ unsigned mapa_rank(unsigned laddr, unsigned r) {
    unsigned a;
    asm("mapa.shared::cluster.u32 %0, %1, %2;" : "=r"(a) : "r"(laddr), "r"(r));
    return a;
}
__device__ __forceinline__ unsigned long long f32x2_add(unsigned long long a, unsigned long long b) {
    unsigned long long r;
    asm("add.rn.f32x2 %0, %1, %2;" : "=l"(r) : "l"(a), "l"(b));
    return r;
}
__device__ __forceinline__ unsigned long long f32x2_mul(unsigned long long a, unsigned long long b) {
    unsigned long long r;
    asm("mul.rn.f32x2 %0, %1, %2;" : "=l"(r) : "l"(a), "l"(b));
    return r;
}
__device__ __forceinline__ unsigned long long pk2(float l, float h) {
    unsigned long long r;
    asm("mov.b64 %0, {%1, %2};" : "=l"(r) : "f"(l), "f"(h));
    return r;
}
__device__ __forceinline__ float lo_f(unsigned long long v) { return __uint_as_float((unsigned)v); }
__device__ __forceinline__ float hi_f(unsigned long long v) { return __uint_as_float((unsigned)(v >> 32)); }

// ---------------- init: zero BN accumulators (graph replays!) ----------------
__global__ void k_init() {
    int t = threadIdx.x;
    if (t < H1D) { g_s1[t] = 0.f; g_ss1[t] = 0.f; }
    if (t < H2D) { g_s2[t] = 0.f; g_ss2[t] = 0.f; }
}

// ---------------- FPS: 8-CTA cluster; REDUX-based reductions; one cluster barrier/iter ----------------
#define FPS_C 8
#define FPS_T 256
#define FPS_PPT 32                       // points per thread
#define FPS_PP2 (FPS_PPT/2)              // packed pairs
#define FPS_W  (FPS_T/32)                // 8 warps

__global__ void __cluster_dims__(FPS_C,1,1) __launch_bounds__(FPS_T,1)
k_fps(const float2* __restrict__ pts, float* __restrict__ cent_dout, int write_dout)
{
    __shared__ unsigned           s_wk[FPS_W];            // per-warp best sv bits
    __shared__ unsigned long long s_wxy[FPS_W];           // per-warp best coords
    __shared__ alignas(16) uint4  s_b[2];                 // CTA best per parity: {sv, pad, xlo, xhi}

    unsigned rank; asm("mov.u32 %0, %%cluster_ctarank;" : "=r"(rank));
    int tid  = threadIdx.x;
    int lane = tid & 31;
    int wid  = tid >> 5;
    int gtid = (int)rank * FPS_T + tid;
    int base = gtid * FPS_PPT;

    // register-resident points (packed pairs) + min-dist^2
    unsigned long long px2[FPS_PP2], py2[FPS_PP2];
    float d2[FPS_PPT];
    {
        const float4* p4 = (const float4*)pts;
        #pragma unroll
        for (int i = 0; i < FPS_PP2; i++) {
            float4 v = p4[(base >> 1) + i];
            px2[i] = pk2(v.x, v.z);
            py2[i] = pk2(v.y, v.w);
            d2[2*i]   = __int_as_float(0x7f800000);
            d2[2*i+1] = __int_as_float(0x7f800000);
        }
    }

    float2 p0 = pts[0];
    float cx = p0.x, cy = p0.y;
    if (rank == 0 && tid == 0) {
        g_cent[0] = p0;
        if (write_dout) { cent_dout[0] = p0.x; cent_dout[1] = p0.y; }
    }

    for (int s = 1; s < M_CENT; s++) {
        int p = s & 1;
        unsigned long long ncx2 = pk2(-cx, -cx);
        unsigned long long ncy2 = pk2(-cy, -cy);

        // scan: update running min-dist^2, track max of mins.
        // prev center's own dd == 0 exactly -> implicit dist.at[prev].set(0)
        float bm = -1.0f;
        #pragma unroll
        for (int i = 0; i < FPS_PP2; i++) {
            unsigned long long dx2 = f32x2_add(px2[i], ncx2);
            unsigned long long dy2 = f32x2_add(py2[i], ncy2);
            unsigned long long dd2 = f32x2_add(f32x2_mul(dx2, dx2), f32x2_mul(dy2, dy2));
            float nd0 = fminf(d2[2*i],   lo_f(dd2));
            float nd1 = fminf(d2[2*i+1], hi_f(dd2));
            d2[2*i]   = nd0;
            d2[2*i+1] = nd1;
            bm = fmaxf(bm, nd0);
            bm = fmaxf(bm, nd1);
        }
        // reference dist domain: sqrt(d2 + 1e-12); sv >= 0 so bits compare as u32
        unsigned sv = __float_as_uint(sqrtf(__fadd_rn(bm, 1e-12f)));

        // single-instruction warp max (latency hides under the match chain below)
        unsigned wmax = __reduce_max_sync(0xFFFFFFFFu, sv);

        // recover coords of FIRST j matching bm (reverse select chain -> smallest j wins)
        float bx = 0.f, by = 0.f;
        #pragma unroll
        for (int i = FPS_PP2 - 1; i >= 0; i--) {
            if (d2[2*i+1] == bm) { bx = hi_f(px2[i]); by = hi_f(py2[i]); }
            if (d2[2*i]   == bm) { bx = lo_f(px2[i]); by = lo_f(py2[i]); }
        }

        // winner lane = lowest lane hitting wmax (lane order == gtid order == point order)
        unsigned wb  = __ballot_sync(0xFFFFFFFFu, sv == wmax);
        int      src = __ffs(wb) - 1;
        float wx = __shfl_sync(0xFFFFFFFFu, bx, src);
        float wy = __shfl_sync(0xFFFFFFFFu, by, src);
        if (lane == 0) { s_wk[wid] = wmax; s_wxy[wid] = pk2(wx, wy); }
        __syncthreads();

        // warp 0: block reduce over 8 warp slots, publish CTA-best mailbox
        if (wid == 0) {
            unsigned k = (lane < FPS_W) ? s_wk[lane] : 0u;
            unsigned bmax = __reduce_max_sync(0xFFFFFFFFu, k);
            unsigned bb   = __ballot_sync(0xFFFFFFFFu, k == bmax);
            int      bsrc = __ffs(bb) - 1;          // lowest warp slot = lowest gtid
            if (lane == 0) {
                unsigned long long bxy = s_wxy[bsrc];
                uint4 m; m.x = bmax; m.y = 0u;
                m.z = (unsigned)bxy; m.w = (unsigned)(bxy >> 32);
                s_b[p] = m;
            }
        }
        // single cluster barrier: releases local mailbox store, acquires peers'
        asm volatile("barrier.cluster.arrive.aligned;" ::: "memory");
        asm volatile("barrier.cluster.wait.aligned;"   ::: "memory");

        // EVERY warp gathers the 8 CTA-bests itself (no block sync afterwards)
        unsigned rk = 0u, rxlo = 0u, rxhi = 0u;
        if (lane < FPS_C) {
            unsigned ra = mapa_rank(smem_u32(&s_b[p]), (unsigned)lane);
            uint4 m;
            asm volatile("ld.shared::cluster.v4.b32 {%0, %1, %2, %3}, [%4];"
                         : "=r"(m.x), "=r"(m.y), "=r"(m.z), "=r"(m.w) : "r"(ra) : "memory");
            rk = m.x; rxlo = m.z; rxhi = m.w;
        }
        unsigned cmax = __reduce_max_sync(0xFFFFFFFFu, rk);
        unsigned cb   = __ballot_sync(0xFFFFFFFFu, rk == cmax);
        int      csrc = __ffs(cb) - 1;              // lowest rank = lowest gtid
        cx = __uint_as_float(__shfl_sync(0xFFFFFFFFu, rxlo, csrc));
        cy = __uint_as_float(__shfl_sync(0xFFFFFFFFu, rxhi, csrc));

        if (rank == 0 && tid == 0) {
            g_cent[s] = make_float2(cx, cy);
            if (write_dout) { cent_dout[2*s] = cx; cent_dout[2*s+1] = cy; }
        }
    }
}

// ---------------- ball query: 1 warp / centroid, first-K by index ----------------
__global__ __launch_bounds__(1024) void k_ballquery(const float2* __restrict__ pts)
{
    int gw   = (blockIdx.x * blockDim.x + threadIdx.x) >> 5;
    int lane = threadIdx.x & 31;
    if (gw >= M_CENT) return;

    float2 c  = g_cent[gw];
    float  c2 = __fadd_rn(__fmul_rn(c.x,c.x), __fmul_rn(c.y,c.y));

    int   cnt  = 0;
    bool  have = false;
    float fx = 0.f, fy = 0.f;

    for (int b = 0; b < N_PTS; b += 32) {
        float2 p   = pts[b + lane];
        float  p2  = __fadd_rn(__fmul_rn(p.x,p.x), __fmul_rn(p.y,p.y));
        float  dot = __fadd_rn(__fmul_rn(c.x,p.x), __fmul_rn(c.y,p.y));
        float  dd  = __fsub_rn(__fadd_rn(c2, p2), __fmul_rn(2.0f, dot));
        bool hit = (dd <= 0.0025f);
        unsigned m = __ballot_sync(0xFFFFFFFFu, hit);
        float rx = __fsub_rn(p.x, c.x), ry = __fsub_rn(p.y, c.y);
        if (!have && m) {
            int src = __ffs(m) - 1;
            fx = __shfl_sync(0xFFFFFFFFu, rx, src);
            fy = __shfl_sync(0xFFFFFFFFu, ry, src);
            have = true;
        }
        int pos = cnt + __popc(m & ((1u << lane) - 1u));
        if (hit && pos < KNN) g_rel[gw*KNN + pos] = make_float2(rx, ry);
        cnt += __popc(m);
        if (cnt >= KNN) break;
    }
    for (int s2 = cnt + lane; s2 < KNN; s2 += 32)
        g_rel[gw*KNN + s2] = make_float2(fx, fy);
}

// ---------------- layer1: freq-encode + [65536x40]@[40x64] + b1 ----------------
__global__ __launch_bounds__(128) void k_layer1(const float* __restrict__ W1,
                                                const float* __restrict__ b1)
{
    __shared__ float ws[IN_DIM*H1D];   // 10 KB
    __shared__ float bs[H1D];
    int tid = threadIdx.x;
    for (int i = tid; i < IN_DIM*H1D; i += 128) ws[i] = W1[i];
    if (tid < H1D) bs[tid] = b1[tid];
    __syncthreads();

    int r = blockIdx.x * 128 + tid;
    float2 q = g_rel[r];

    float acc[H1D];
    #pragma unroll
    for (int j = 0; j < H1D; j++) acc[j] = bs[j];

    for (int f = 0; f < 10; f++) {
        float fr = 3.14159265358979f * (float)(1 << f);
        float e0, e1, e2, e3;
        sincosf(__fmul_rn(q.x, fr), &e0, &e1);
        sincosf(__fmul_rn(q.y, fr), &e2, &e3);
        const float* w0 = &ws[(4*f + 0)*H1D];
        const float* w1 = &ws[(4*f + 1)*H1D];
        const float* w2 = &ws[(4*f + 2)*H1D];
        const float* w3 = &ws[(4*f + 3)*H1D];
        #pragma unroll
        for (int j = 0; j < H1D; j++) {
            acc[j] = fmaf(e0, w0[j], acc[j]);
            acc[j] = fmaf(e1, w1[j], acc[j]);
            acc[j] = fmaf(e2, w2[j], acc[j]);
            acc[j] = fmaf(e3, w3[j], acc[j]);
        }
    }
    float4* o = (float4*)&g_h1[(size_t)r * H1D];
    #pragma unroll
    for (int j = 0; j < H1D/4; j++)
        o[j] = make_float4(acc[4*j], acc[4*j+1], acc[4*j+2], acc[4*j+3]);
}

// ---------------- column sum / sumsq reduction ----------------
template <int C>
__device__ __forceinline__ void colreduce_body(const float* __restrict__ src,
                                               float* __restrict__ outs,
                                               float* __restrict__ outss)
{
    __shared__ float sh_s[256], sh_q[256];
    int tid = threadIdx.x;
    int col = tid & (C - 1);
    int sub = tid / C;
    const int L = 256 / C;
    int row0 = blockIdx.x * (NROWS / 256);
    float s = 0.f, q = 0.f;
    for (int r = sub; r < NROWS/256; r += L) {
        float v = src[(size_t)(row0 + r) * C + col];
        s += v;
        q  = fmaf(v, v, q);
    }
    sh_s[tid] = s; sh_q[tid] = q;
    __syncthreads();
    if (tid < C) {
        float ts = 0.f, tq = 0.f;
        #pragma unroll
        for (int u = 0; u < L; u++) { ts += sh_s[u*C + tid]; tq += sh_q[u*C + tid]; }
        atomicAdd(&outs[tid], ts);
        atomicAdd(&outss[tid], tq);
    }
}
__global__ __launch_bounds__(256) void k_red1() { colreduce_body<H1D>(g_h1, g_s1, g_ss1); }
__global__ __launch_bounds__(256) void k_red2() { colreduce_body<H2D>(g_h2, g_s2, g_ss2); }

// ---------------- layer2: BN1+ReLU then [65536x64]@[64x128] + b2 ----------------
__global__ __launch_bounds__(128) void k_layer2(const float* __restrict__ W2,
                                                const float* __restrict__ b2,
                                                const float* __restrict__ g1,
                                                const float* __restrict__ be1)
{
    __shared__ float xs[32*H1D];
    __shared__ float sc[H1D], sh[H1D];
    int tid = threadIdx.x;
    if (tid < H1D) {
        float m  = g_s1[tid]  * (1.0f/NROWS);
        float v  = g_ss1[tid] * (1.0f/NROWS) - m*m;
        float rs = rsqrtf(v + 1e-5f);
        float scale = g1[tid] * rs;
        sc[tid] = scale;
        sh[tid] = be1[tid] - m * scale;
    }
    __syncthreads();

    int row0 = blockIdx.x * 32;
    for (int t = tid; t < 32*H1D; t += 128) {
        int c = t & (H1D - 1);
        float v = g_h1[(size_t)row0 * H1D + t];
        xs[t] = fmaxf(fmaf(v, sc[c], sh[c]), 0.0f);
    }
    __syncthreads();

    int j = tid;
    float acc[32];
    float bj = b2[j];
    #pragma unroll
    for (int r = 0; r < 32; r++) acc[r] = bj;
    for (int i = 0; i < H1D; i++) {
        float w = __ldg(&W2[i*H2D + j]);
        #pragma unroll
        for (int r = 0; r < 32; r++)
            acc[r] = fmaf(xs[r*H1D + i], w, acc[r]);
    }
    #pragma unroll
    for (int r = 0; r < 32; r++)
        g_h2[(size_t)(row0 + r) * H2D + j] = acc[r];
}

// ---------------- layer3: BN2+ReLU, [32x128]@[128x128]+b3, max over 32 ----------------
__global__ __launch_bounds__(128) void k_layer3(const float* __restrict__ W3,
                                                const float* __restrict__ b3,
                                                const float* __restrict__ g2,
                                                const float* __restrict__ be2,
                                                float* __restrict__ out)
{
    __shared__ float xs[32*H2D];
    __shared__ float sc[H2D], sh[H2D];
    int tid = threadIdx.x;
    {
        float m  = g_s2[tid]  * (1.0f/NROWS);
        float v  = g_ss2[tid] * (1.0f/NROWS) - m*m;
        float rs = rsqrtf(v + 1e-5f);
        float scale = g2[tid] * rs;
        sc[tid] = scale;
        sh[tid] = be2[tid] - m * scale;
    }
    __syncthreads();

    int row0 = blockIdx.x * 32;
    for (int t = tid; t < 32*H2D; t += 128) {
        int c = t & (H2D - 1);
        float v = g_h2[(size_t)row0 * H2D + t];
        xs[t] = fmaxf(fmaf(v, sc[c], sh[c]), 0.0f);
    }
    __syncthreads();

    int j = tid;
    float acc[32];
    float bj = b3[j];
    #pragma unroll
    for (int r = 0; r < 32; r++) acc[r] = bj;
    for (int i = 0; i < H2D; i++) {
        float w = __ldg(&W3[i*OUTD + j]);
        #pragma unroll
        for (int r = 0; r < 32; r++)
            acc[r] = fmaf(xs[r*H2D + i], w, acc[r]);
    }
    float mv = acc[0];
    #pragma unroll
    for (int r = 1; r < 32; r++) mv = fmaxf(mv, acc[r]);
    out[(size_t)blockIdx.x * OUTD + j] = mv;
}

// ---------------- launch ----------------
extern "C" void kernel_launch(void* const* d_in, const int* in_sizes, int n_in,
                              void* d_out, int out_size)
{
    const float2* pts = (const float2*)d_in[0];
    const float* W1  = (const float*)d_in[1];
    const float* b1  = (const float*)d_in[2];
    const float* g1  = (const float*)d_in[3];
    const float* be1 = (const float*)d_in[4];
    const float* W2  = (const float*)d_in[5];
    const float* b2  = (const float*)d_in[6];
    const float* g2  = (const float*)d_in[7];
    const float* be2 = (const float*)d_in[8];
    const float* W3  = (const float*)d_in[9];
    const float* b3  = (const float*)d_in[10];

    float* out = (float*)d_out;
    float* cent_out = out + (size_t)M_CENT * OUTD;
    int wd = (out_size >= M_CENT*OUTD + M_CENT*2) ? 1 : 0;

    k_init<<<1, 128>>>();
    k_fps<<<FPS_C, FPS_T>>>(pts, cent_out, wd);
    k_ballquery<<<64, 1024>>>(pts);
    k_layer1<<<NROWS/128, 128>>>(W1, b1);
    k_red1<<<256, 256>>>();
    k_layer2<<<NROWS/32, 128>>>(W2, b2, g1, be1);
    k_red2<<<256, 256>>>();
    k_layer3<<<M_CENT, 128>>>(W3, b3, g2, be2, out);
}